// round 3
// baseline (speedup 1.0000x reference)
#include <cuda_runtime.h>
#include <cuda_bf16.h>

#define Bn 256
#define Ln 1024
#define En 128
#define Hn 256
#define Vn 64

// ---- device-global scratch (no allocations allowed) ----
__device__ float g_proj[Vn * Hn];                    // token -> x_proj row (b_e folded in)
__device__ float g_hout[(size_t)Bn * Ln * Hn];       // all hidden states, 268MB
__device__ int   g_x_is32;

// ---------------- f32x2 helpers (Blackwell packed fp32) ----------------
__device__ __forceinline__ void ffma2(unsigned long long& acc,
                                      unsigned long long a, unsigned long long b) {
    asm("fma.rn.f32x2 %0, %1, %2, %0;" : "+l"(acc) : "l"(a), "l"(b));
}
__device__ __forceinline__ unsigned long long pack2u(unsigned int lo, unsigned int hi) {
    unsigned long long r;
    asm("mov.b64 %0, {%1, %2};" : "=l"(r) : "r"(lo), "r"(hi));
    return r;
}
__device__ __forceinline__ unsigned long long dup2f(float a) {
    unsigned int u = __float_as_uint(a);
    return pack2u(u, u);
}
__device__ __forceinline__ float2 unpack2(unsigned long long v) {
    unsigned int lo, hi;
    asm("mov.b64 {%0, %1}, %2;" : "=r"(lo), "=r"(hi) : "l"(v));
    return make_float2(__uint_as_float(lo), __uint_as_float(hi));
}
// expand bf16x2 reg (k0 lo | k1 hi) into f32x2 pair (k0, k1)
__device__ __forceinline__ unsigned long long wpair(unsigned int w) {
    return pack2u(w << 16, w & 0xffff0000u);
}
__device__ __forceinline__ float tanh_fast(float x) {
    float e = __expf(x + x);
    return 1.0f - __fdividef(2.0f, e + 1.0f);
}

// ---------------- dtype detection ----------------
__global__ void k_reset() { g_x_is32 = 0; }

__global__ void k_detect(const unsigned int* __restrict__ xw) {
    int i = blockIdx.x * blockDim.x + threadIdx.x;
    int idx = 2 * i + 1;                 // odd 32-bit words
    if (idx < Bn * Ln) {
        if (xw[idx] != 0u) g_x_is32 = 1; // int64 high halves are all zero (vals 0..63)
    }
}

// ---------------- projection table ----------------
// proj[v][h] = sum_e emb[v][e] * W_e[h][e] + b_e[h]
__global__ void k_proj(const float* __restrict__ emb, const float* __restrict__ We,
                       const float* __restrict__ be) {
    __shared__ float es[En];
    int v = blockIdx.x, j = threadIdx.x;
    if (j < En) es[j] = emb[v * En + j];
    __syncthreads();
    float acc = 0.f;
    #pragma unroll
    for (int e = 0; e < En; e++) acc = fmaf(es[e], We[j * En + e], acc);
    g_proj[v * Hn + j] = acc + be[j];
}

// ---------------- recurrence ----------------
// 128 CTAs x 256 threads. CTA owns batches (2c, 2c+1) for the full 1024-step chain.
// W_h row j lives in REGISTERS of thread j as 128 bf16x2 words. Only the 1KB
// h vectors live in (double-buffered) smem. Inner loop uses packed fma.rn.f32x2.
__global__ void __launch_bounds__(256, 1) k_rnn(const void* __restrict__ xraw,
        const float* __restrict__ hidden, const float* __restrict__ Wh,
        const float* __restrict__ bh, float* __restrict__ dout, int write_final) {
    __shared__ __align__(16) float hs[2 * 2 * Hn];   // [buf][batch][256]
    const int j  = threadIdx.x;
    const int b0 = 2 * blockIdx.x, b1 = b0 + 1;
    const int is32 = g_x_is32;
    const int* x32       = (const int*)xraw;
    const long long* x64 = (const long long*)xraw;

    // load my W_h row into registers (bf16x2 packed)
    unsigned int wreg[128];
    const float4* Wh4 = (const float4*)Wh;
    #pragma unroll
    for (int q = 0; q < 64; q++) {
        float4 w4 = Wh4[j * 64 + q];
        __nv_bfloat162 lo2 = __floats2bfloat162_rn(w4.x, w4.y);
        __nv_bfloat162 hi2 = __floats2bfloat162_rn(w4.z, w4.w);
        wreg[2 * q]     = *(unsigned int*)&lo2;
        wreg[2 * q + 1] = *(unsigned int*)&hi2;
    }

    hs[j]       = hidden[b0 * Hn + j];
    hs[Hn + j]  = hidden[b1 * Hn + j];
    const float bhj = bh[j];
    __syncthreads();

    float fin0 = 0.f, fin1 = 0.f;
    for (int t = 0; t < Ln; t++) {
        const int cur = t & 1;
        // prefetch token + x_proj early (long latency hidden under the matvec)
        int tok0 = is32 ? x32[b0 * Ln + t] : (int)x64[b0 * Ln + t];
        int tok1 = is32 ? x32[b1 * Ln + t] : (int)x64[b1 * Ln + t];
        float xp0 = g_proj[tok0 * Hn + j];
        float xp1 = g_proj[tok1 * Hn + j];

        const ulonglong2* h0 = (const ulonglong2*)(hs + cur * 2 * Hn);       // batch0 pairs
        const ulonglong2* h1 = (const ulonglong2*)(hs + cur * 2 * Hn + Hn);  // batch1 pairs

        unsigned long long a00 = 0ull, a01 = 0ull, a10 = 0ull, a11 = 0ull;
        #pragma unroll
        for (int q = 0; q < 64; q++) {
            unsigned long long wp0 = wpair(wreg[2 * q]);       // (w[4q],   w[4q+1])
            unsigned long long wp1 = wpair(wreg[2 * q + 1]);   // (w[4q+2], w[4q+3])
            ulonglong2 p0 = h0[q];                             // (h[4q..4q+3]) batch0
            ulonglong2 p1 = h1[q];                             // batch1
            ffma2(a00, wp0, p0.x); ffma2(a01, wp1, p0.y);
            ffma2(a10, wp0, p1.x); ffma2(a11, wp1, p1.y);
        }
        float2 s0 = unpack2(a00), s1 = unpack2(a01);
        float2 s2 = unpack2(a10), s3 = unpack2(a11);
        float nh0 = tanh_fast((s0.x + s0.y) + (s1.x + s1.y) + xp0 + bhj);
        float nh1 = tanh_fast((s2.x + s2.y) + (s3.x + s3.y) + xp1 + bhj);

        g_hout[((size_t)b0 * Ln + t) * Hn + j] = nh0;
        g_hout[((size_t)b1 * Ln + t) * Hn + j] = nh1;
        const int nxt = cur ^ 1;
        hs[nxt * 2 * Hn + j]      = nh0;
        hs[nxt * 2 * Hn + Hn + j] = nh1;
        fin0 = nh0; fin1 = nh1;
        __syncthreads();
    }
    if (write_final) {
        dout[(size_t)Bn * Ln * Vn + b0 * Hn + j] = fin0;
        dout[(size_t)Bn * Ln * Vn + b1 * Hn + j] = fin1;
    }
}

// ---------------- logits GEMM ----------------
// logits[r][v] = sum_k hout[r][k] * fcw[v][k] + fcb[v]
// fcw^T and a k-major (transposed) 64-row h tile in smem; 4x4 register tile
// per thread with packed f32x2 FMAs over row pairs.
#define LOG_SMEM (65536 + 65536)

__global__ void __launch_bounds__(256, 1) k_logits(const float* __restrict__ fcw,
        const float* __restrict__ fcb, float* __restrict__ out) {
    extern __shared__ float smf[];
    float* fT = smf;             // [256][64]  fT[k][v] = fcw[v][k]
    float* hT = smf + 16384;     // [256][64]  hT[k][row]
    const int tid = threadIdx.x;
    const int tx = tid & 15, ty = tid >> 4;

    for (int p = tid; p < Vn * Hn; p += 256) {   // conflict-free transposed fill
        int v = p & 63, k = p >> 6;
        fT[k * 64 + v] = fcw[v * Hn + k];
    }
    float4 bias = ((const float4*)fcb)[tx];
    __syncthreads();

    const int ntiles = (Bn * Ln) / 64;      // 4096
    for (int tile = blockIdx.x; tile < ntiles; tile += gridDim.x) {
        const float4* src = (const float4*)(g_hout + (size_t)tile * 64 * Hn);
        for (int p = tid; p < 64 * 64; p += 256) {
            int row = p & 63, kc = p >> 6;            // row fastest: conflict-free STS
            float4 v = src[row * 64 + kc];
            hT[(4 * kc + 0) * 64 + row] = v.x;
            hT[(4 * kc + 1) * 64 + row] = v.y;
            hT[(4 * kc + 2) * 64 + row] = v.z;
            hT[(4 * kc + 3) * 64 + row] = v.w;
        }
        __syncthreads();

        // acc[rp][c]: rp=0 -> rows (4ty, 4ty+1); rp=1 -> rows (4ty+2, 4ty+3)
        unsigned long long a00 = 0ull, a01 = 0ull, a02 = 0ull, a03 = 0ull;
        unsigned long long a10 = 0ull, a11 = 0ull, a12 = 0ull, a13 = 0ull;

        #pragma unroll 8
        for (int k = 0; k < Hn; k++) {
            ulonglong2 ap = ((const ulonglong2*)(hT + k * 64))[ty];  // rows 4ty..4ty+3
            float4 b4 = ((const float4*)(fT + k * 64))[tx];
            unsigned long long bd0 = dup2f(b4.x), bd1 = dup2f(b4.y);
            unsigned long long bd2 = dup2f(b4.z), bd3 = dup2f(b4.w);
            ffma2(a00, ap.x, bd0); ffma2(a01, ap.x, bd1);
            ffma2(a02, ap.x, bd2); ffma2(a03, ap.x, bd3);
            ffma2(a10, ap.y, bd0); ffma2(a11, ap.y, bd1);
            ffma2(a12, ap.y, bd2); ffma2(a13, ap.y, bd3);
        }

        float2 c00 = unpack2(a00), c01 = unpack2(a01), c02 = unpack2(a02), c03 = unpack2(a03);
        float2 c10 = unpack2(a10), c11 = unpack2(a11), c12 = unpack2(a12), c13 = unpack2(a13);
        size_t base = ((size_t)tile * 64 + 4 * ty) * 64 + 4 * tx;
        float4 o;
        o.x = c00.x + bias.x; o.y = c01.x + bias.y; o.z = c02.x + bias.z; o.w = c03.x + bias.w;
        *(float4*)(out + base + 0 * 64) = o;
        o.x = c00.y + bias.x; o.y = c01.y + bias.y; o.z = c02.y + bias.z; o.w = c03.y + bias.w;
        *(float4*)(out + base + 1 * 64) = o;
        o.x = c10.x + bias.x; o.y = c11.x + bias.y; o.z = c12.x + bias.z; o.w = c13.x + bias.w;
        *(float4*)(out + base + 2 * 64) = o;
        o.x = c10.y + bias.x; o.y = c11.y + bias.y; o.z = c12.y + bias.z; o.w = c13.y + bias.w;
        *(float4*)(out + base + 3 * 64) = o;
        __syncthreads();
    }
}

// ---------------- launch ----------------
extern "C" void kernel_launch(void* const* d_in, const int* in_sizes, int n_in,
                              void* d_out, int out_size) {
    const void*  x      = d_in[0];
    const float* hidden = (const float*)d_in[1];
    const float* emb    = (const float*)d_in[2];
    const float* We     = (const float*)d_in[3];
    const float* be     = (const float*)d_in[4];
    const float* Wh     = (const float*)d_in[5];
    const float* bhp    = (const float*)d_in[6];
    const float* fcw    = (const float*)d_in[7];
    const float* fcb    = (const float*)d_in[8];
    float* out = (float*)d_out;

    cudaFuncSetAttribute(k_logits, cudaFuncAttributeMaxDynamicSharedMemorySize, LOG_SMEM);

    k_reset<<<1, 1>>>();
    k_detect<<<(Bn * Ln / 2 + 255) / 256, 256>>>((const unsigned int*)x);
    k_proj<<<Vn, Hn>>>(emb, We, be);

    int write_final = (out_size >= Bn * Ln * Vn + Bn * Hn) ? 1 : 0;
    k_rnn<<<Bn / 2, Hn>>>(x, hidden, Wh, bhp, out, write_final);
    k_logits<<<148, 256, LOG_SMEM>>>(fcw, fcb, out);
}